// round 2
// baseline (speedup 1.0000x reference)
#include <cuda_runtime.h>

// Problem constants
#define BB 4
#define TT 4096
#define DD 1024
#define HH 16
#define HD 64
#define MM (BB*TT)     // 16384 rows

// ---------------- scratch (device globals; no allocation allowed) ----------
__device__ float g_q[(size_t)BB*HH*TT*HD];     // (b,h,t,e)  64 MB
__device__ float g_k[(size_t)BB*HH*TT*HD];     // (b,h,t,e)  64 MB
__device__ float g_v[(size_t)BB*HH*TT*HD];     // (b,h,t,e)  64 MB
__device__ float g_attn[(size_t)MM*DD];        // (b,t,d)    64 MB
__device__ float g_kv[BB*HH*HD*HD];            // 1 MB
__device__ float g_ksum[BB*HH*HD];             // 16 KB

// ---------------------------------------------------------------------------
// SGEMM: C = A(MxK) * W^T (W is NxK row-major), M=16384, N=K=1024.
// EPI: 0 = plain write d_out[m*D+n]          (A = g_attn)
//      1 = phi(acc)        -> g_q (b,h,t,e)
//      2 = phi(acc)*mask   -> g_k
//      3 = acc*mask        -> g_v
// mask is int32 (bool promoted by harness); nonzero => zero the row.
// ---------------------------------------------------------------------------
template<int EPI>
__global__ __launch_bounds__(256)
void sgemm_k(const float* __restrict__ Ax, const float* __restrict__ W,
             const int* __restrict__ mask, float* __restrict__ outp)
{
    __shared__ float As[16][132];
    __shared__ float Bs[16][132];

    const float* A = (EPI == 0) ? (const float*)g_attn : Ax;
    float* out;
    if      (EPI == 0) out = outp;
    else if (EPI == 1) out = g_q;
    else if (EPI == 2) out = g_k;
    else               out = g_v;

    const int tid = threadIdx.x;
    const int m0 = blockIdx.y * 128;
    const int n0 = blockIdx.x * 128;
    const int tx = tid & 15;        // col group
    const int ty = tid >> 4;        // row group

    float acc[8][8];
    #pragma unroll
    for (int i = 0; i < 8; i++)
        #pragma unroll
        for (int j = 0; j < 8; j++) acc[i][j] = 0.f;

    for (int k0 = 0; k0 < DD; k0 += 16) {
        // load 128x16 tiles of A and W (transposed into smem)
        #pragma unroll
        for (int l = 0; l < 2; l++) {
            int f = tid + l * 256;              // float4 id 0..511
            int row = f >> 2;                   // 0..127
            int kq  = (f & 3) * 4;              // 0,4,8,12
            float4 av = *(const float4*)(A + (size_t)(m0 + row) * DD + k0 + kq);
            float4 bv = *(const float4*)(W + (size_t)(n0 + row) * DD + k0 + kq);
            As[kq + 0][row] = av.x; As[kq + 1][row] = av.y;
            As[kq + 2][row] = av.z; As[kq + 3][row] = av.w;
            Bs[kq + 0][row] = bv.x; Bs[kq + 1][row] = bv.y;
            Bs[kq + 2][row] = bv.z; Bs[kq + 3][row] = bv.w;
        }
        __syncthreads();

        #pragma unroll
        for (int kk = 0; kk < 16; kk++) {
            float a[8], b[8];
            #pragma unroll
            for (int i = 0; i < 8; i++) { a[i] = As[kk][ty * 8 + i]; b[i] = Bs[kk][tx * 8 + i]; }
            #pragma unroll
            for (int i = 0; i < 8; i++)
                #pragma unroll
                for (int j = 0; j < 8; j++) acc[i][j] += a[i] * b[j];
        }
        __syncthreads();
    }

    // ---- fused epilogue ----
    #pragma unroll
    for (int i = 0; i < 8; i++) {
        int m = m0 + ty * 8 + i;
        float mz = 1.f;
        if (EPI == 2 || EPI == 3) mz = (mask[m] != 0) ? 0.f : 1.f;
        int b_ = m >> 12;
        int t  = m & (TT - 1);
        #pragma unroll
        for (int j = 0; j < 8; j++) {
            int n = n0 + tx * 8 + j;
            float v = acc[i][j];
            if (EPI == 1 || EPI == 2) v = (v > 0.f) ? (v + 1.f) : __expf(v);  // elu+1
            if (EPI == 2 || EPI == 3) v *= mz;
            if (EPI == 0) {
                out[(size_t)m * DD + n] = v;
            } else {
                int h = n >> 6, e = n & 63;
                out[(((size_t)(b_ * HH + h)) * TT + t) * HD + e] = v;
            }
        }
    }
}

// ---------------------------------------------------------------------------
// zero kv / ksum accumulators (graph replays must be deterministic)
// ---------------------------------------------------------------------------
__global__ void zero_kv_kernel()
{
    int i = blockIdx.x * 256 + threadIdx.x;
    if (i < BB * HH * HD * HD) g_kv[i] = 0.f;
    if (i < BB * HH * HD)      g_ksum[i] = 0.f;
}

// ---------------------------------------------------------------------------
// kv[b,h,d,e] = sum_t k[t,d] * v[t,e];  ksum[b,h,d] = sum_t k[t,d]
// grid (64 bh, NCH t-chunks); 128 threads = 2 groups of 64; each group handles
// its own t-rows with an 8x8 per-thread tile.
// ---------------------------------------------------------------------------
#define KV_NCH 8
__global__ __launch_bounds__(128)
void kv_kernel()
{
    const int bh  = blockIdx.x;
    const int ch  = blockIdx.y;
    const int tid = threadIdx.x;
    const int grp = tid >> 6;
    const int gt  = tid & 63;
    const int d0  = (gt >> 3) * 8;
    const int e0  = (gt & 7) * 8;
    const int RPB = TT / KV_NCH;     // rows per block
    const int RPG = RPB / 2;         // rows per group

    const float* kp = g_k + ((size_t)bh * TT + ch * RPB + grp * RPG) * HD;
    const float* vp = g_v + ((size_t)bh * TT + ch * RPB + grp * RPG) * HD;

    __shared__ float ks[2][8][64];
    __shared__ float vs[2][8][64];

    float acc[8][8];
    #pragma unroll
    for (int i = 0; i < 8; i++)
        #pragma unroll
        for (int j = 0; j < 8; j++) acc[i][j] = 0.f;
    float ksacc = 0.f;

    for (int t0 = 0; t0 < RPG; t0 += 8) {
        #pragma unroll
        for (int l = 0; l < 2; l++) {
            int f = gt + l * 64;               // float4 id 0..127 (8*64/4)
            int r = f >> 4, c = (f & 15) * 4;
            *(float4*)&ks[grp][r][c] = *(const float4*)(kp + (size_t)(t0 + r) * HD + c);
            *(float4*)&vs[grp][r][c] = *(const float4*)(vp + (size_t)(t0 + r) * HD + c);
        }
        __syncthreads();
        #pragma unroll
        for (int tt = 0; tt < 8; tt++) {
            float kr[8], vr[8];
            *(float4*)(kr)     = *(const float4*)&ks[grp][tt][d0];
            *(float4*)(kr + 4) = *(const float4*)&ks[grp][tt][d0 + 4];
            *(float4*)(vr)     = *(const float4*)&vs[grp][tt][e0];
            *(float4*)(vr + 4) = *(const float4*)&vs[grp][tt][e0 + 4];
            #pragma unroll
            for (int i = 0; i < 8; i++)
                #pragma unroll
                for (int j = 0; j < 8; j++) acc[i][j] += kr[i] * vr[j];
            ksacc += ks[grp][tt][gt];
        }
        __syncthreads();
    }

    float* kvp = g_kv + (size_t)bh * HD * HD;
    #pragma unroll
    for (int i = 0; i < 8; i++)
        #pragma unroll
        for (int j = 0; j < 8; j++)
            atomicAdd(&kvp[(d0 + i) * HD + e0 + j], acc[i][j]);
    atomicAdd(&g_ksum[bh * HD + gt], ksacc);
}

// ---------------------------------------------------------------------------
// out[b,h,t,e] = (q[t,:] @ kv) / max(q[t,:].k_sum, 1e-6); write to (b,t,d)
// grid (T/128, 64 bh); 256 threads; thread = (row, 32-col half); kv broadcast
// from smem, q streamed via LDG.128.
// ---------------------------------------------------------------------------
__global__ __launch_bounds__(256)
void out_kernel()
{
    const int bh  = blockIdx.y;
    const int t0  = blockIdx.x * 128;
    const int tid = threadIdx.x;

    __shared__ float kvs[64][64];
    __shared__ float kss[64];

    const float* kvp = g_kv + (size_t)bh * HD * HD;
    #pragma unroll
    for (int l = 0; l < 4; l++) {
        int f = tid + l * 256;                 // float4 id 0..1023
        int r = f >> 4, c = (f & 15) * 4;
        *(float4*)&kvs[r][c] = *(const float4*)(kvp + r * HD + c);
    }
    if (tid < 64) kss[tid] = g_ksum[bh * HD + tid];
    __syncthreads();

    const int row = tid >> 1;
    const int c0  = (tid & 1) * 32;
    const float* qp = g_q + ((size_t)bh * TT + t0 + row) * HD;

    float acc[32];
    #pragma unroll
    for (int j = 0; j < 32; j++) acc[j] = 0.f;
    float norm = 0.f;

    #pragma unroll
    for (int dq = 0; dq < 64; dq += 4) {
        float4 q4 = *(const float4*)(qp + dq);
        float qa[4] = {q4.x, q4.y, q4.z, q4.w};
        #pragma unroll
        for (int s = 0; s < 4; s++) {
            int d = dq + s;
            norm += qa[s] * kss[d];
            #pragma unroll
            for (int j = 0; j < 32; j++) acc[j] += qa[s] * kvs[d][c0 + j];
        }
    }

    float inv = 1.f / fmaxf(norm, 1e-6f);
    const int b_ = bh >> 4, h = bh & 15;
    float* op = g_attn + ((size_t)b_ * TT + t0 + row) * DD + h * HD + c0;
    #pragma unroll
    for (int j = 0; j < 32; j++) op[j] = acc[j] * inv;
}

// ---------------------------------------------------------------------------
extern "C" void kernel_launch(void* const* d_in, const int* in_sizes, int n_in,
                              void* d_out, int out_size)
{
    const float* x  = (const float*)d_in[0];
    const int*   mk = (const int*)d_in[1];       // bool mask promoted to int32
    const float* Wq = (const float*)d_in[2];
    const float* Wk = (const float*)d_in[3];
    const float* Wv = (const float*)d_in[4];
    const float* Wo = (const float*)d_in[5];
    float* out      = (float*)d_out;

    dim3 gg(DD / 128, MM / 128);   // (8, 128)

    sgemm_k<1><<<gg, 256>>>(x, Wq, mk, nullptr);   // q = phi(x Wq^T)
    sgemm_k<2><<<gg, 256>>>(x, Wk, mk, nullptr);   // k = phi(x Wk^T) * mask
    sgemm_k<3><<<gg, 256>>>(x, Wv, mk, nullptr);   // v = (x Wv^T) * mask

    zero_kv_kernel<<<(BB * HH * HD * HD + 255) / 256, 256>>>();
    kv_kernel<<<dim3(BB * HH, KV_NCH), 128>>>();
    out_kernel<<<dim3(TT / 128, BB * HH), 256>>>();

    sgemm_k<0><<<gg, 256>>>(nullptr, Wo, mk, out); // y = attn Wo^T
}

// round 6
// speedup vs baseline: 1.9823x; 1.9823x over previous
#include <cuda_runtime.h>
#include <cuda_bf16.h>
#include <cstdint>

// Problem constants
#define BB 4
#define TT 4096
#define DD 1024
#define HH 16
#define HD 64
#define MM (BB*TT)     // 16384 rows

// ---------------- scratch (device globals; no allocation allowed) ----------
__device__ float g_q[(size_t)BB*HH*TT*HD];     // (b,h,t,e)  64 MB
__device__ float g_k[(size_t)BB*HH*TT*HD];     // (b,h,t,e)  64 MB
__device__ float g_v[(size_t)BB*HH*TT*HD];     // (b,h,t,e)  64 MB
__device__ float g_attn[(size_t)MM*DD];        // (b,t,d)    64 MB
__device__ float g_kv[BB*HH*HD*HD];            // 1 MB
__device__ float g_ksum[BB*HH*HD];             // 16 KB

// ---------------------------------------------------------------------------
// bf16 mma.sync m16n8k16 (sm_80 base PTX -- valid on plain sm_100 target)
// ---------------------------------------------------------------------------
__device__ __forceinline__ void mma_bf16(float* c, const uint32_t* a, const uint32_t* b) {
    asm volatile(
        "mma.sync.aligned.m16n8k16.row.col.f32.bf16.bf16.f32 "
        "{%0,%1,%2,%3}, {%4,%5,%6,%7}, {%8,%9}, {%0,%1,%2,%3};"
        : "+f"(c[0]), "+f"(c[1]), "+f"(c[2]), "+f"(c[3])
        : "r"(a[0]), "r"(a[1]), "r"(a[2]), "r"(a[3]), "r"(b[0]), "r"(b[1]));
}

// split float4 -> bf16 hi + bf16 lo, packed 2-per-u32 (low half = even elem)
__device__ __forceinline__ void cvt_pair(float4 v, uint2& hi, uint2& lo) {
    __nv_bfloat16 h0 = __float2bfloat16(v.x), h1 = __float2bfloat16(v.y);
    __nv_bfloat16 h2 = __float2bfloat16(v.z), h3 = __float2bfloat16(v.w);
    __nv_bfloat16 l0 = __float2bfloat16(v.x - __bfloat162float(h0));
    __nv_bfloat16 l1 = __float2bfloat16(v.y - __bfloat162float(h1));
    __nv_bfloat16 l2 = __float2bfloat16(v.z - __bfloat162float(h2));
    __nv_bfloat16 l3 = __float2bfloat16(v.w - __bfloat162float(h3));
    hi.x = (uint32_t)__bfloat16_as_ushort(h0) | ((uint32_t)__bfloat16_as_ushort(h1) << 16);
    hi.y = (uint32_t)__bfloat16_as_ushort(h2) | ((uint32_t)__bfloat16_as_ushort(h3) << 16);
    lo.x = (uint32_t)__bfloat16_as_ushort(l0) | ((uint32_t)__bfloat16_as_ushort(l1) << 16);
    lo.y = (uint32_t)__bfloat16_as_ushort(l2) | ((uint32_t)__bfloat16_as_ushort(l3) << 16);
}

#define ROW32   20                    // u32 per smem row (80 B, bank-conflict-free)
#define TILE32  (128*ROW32)           // one 128x32-bf16 tile (10240 B)
#define BUF32   (4*TILE32)            // Ahi, Alo, Bhi, Blo = 40960 B (static smem)

__device__ __forceinline__ void store_chunk(uint32_t* base, int tid,
                                            const float4* pa, const float4* pb) {
    #pragma unroll
    for (int l = 0; l < 4; l++) {
        int f = tid + l * 256;
        int row = f >> 3, c4 = (f & 7) << 2;
        int idx = row * ROW32 + (c4 >> 1);
        uint2 hi, lo;
        cvt_pair(pa[l], hi, lo);
        *(uint2*)(base + idx)              = hi;
        *(uint2*)(base + TILE32 + idx)     = lo;
        cvt_pair(pb[l], hi, lo);
        *(uint2*)(base + 2 * TILE32 + idx) = hi;
        *(uint2*)(base + 3 * TILE32 + idx) = lo;
    }
}

// ---------------------------------------------------------------------------
// C = A(MxK) * W^T via 3x-bf16-split mma.sync; tile 128x128, K-chunk 32.
// Single static smem buffer; next chunk prefetched into registers during the
// mma loop, so the sync count per iteration matches a double-buffered layout.
// EPI: 0 plain->d_out, 1 phi->g_q, 2 phi*mask->g_k, 3 *mask->g_v
// ---------------------------------------------------------------------------
template<int EPI>
__global__ __launch_bounds__(256, 1)
void sgemm_mma(const float* __restrict__ Ax, const float* __restrict__ W,
               const int* __restrict__ mask, float* __restrict__ outp)
{
    __shared__ uint32_t smu[BUF32];
    const int tid  = threadIdx.x;
    const int wid  = tid >> 5, lane = tid & 31;
    const int g    = lane >> 2, q = lane & 3;
    const int m0   = blockIdx.y * 128;
    const int n0   = blockIdx.x * 128;
    const int wr   = (wid >> 2) * 64;
    const int wc   = (wid & 3) * 32;

    const float* A = (EPI == 0) ? (const float*)g_attn : Ax;
    float* out;
    if      (EPI == 0) out = outp;
    else if (EPI == 1) out = g_q;
    else if (EPI == 2) out = g_k;
    else               out = g_v;

    float acc[4][4][4];
    #pragma unroll
    for (int i = 0; i < 4; i++)
        #pragma unroll
        for (int j = 0; j < 4; j++)
            #pragma unroll
            for (int r = 0; r < 4; r++) acc[i][j][r] = 0.f;

    // prologue: chunk 0
    float4 pa[4], pb[4];
    #pragma unroll
    for (int l = 0; l < 4; l++) {
        int f = tid + l * 256;
        int row = f >> 3, c4 = (f & 7) << 2;
        pa[l] = *(const float4*)(A + (size_t)(m0 + row) * DD + c4);
        pb[l] = *(const float4*)(W + (size_t)(n0 + row) * DD + c4);
    }
    store_chunk(smu, tid, pa, pb);
    __syncthreads();

    for (int kc = 0; kc < 32; kc++) {
        if (kc < 31) {
            const int k0 = (kc + 1) * 32;
            #pragma unroll
            for (int l = 0; l < 4; l++) {
                int f = tid + l * 256;
                int row = f >> 3, c4 = (f & 7) << 2;
                pa[l] = *(const float4*)(A + (size_t)(m0 + row) * DD + k0 + c4);
                pb[l] = *(const float4*)(W + (size_t)(n0 + row) * DD + k0 + c4);
            }
        }

        const uint32_t* Ah = smu;
        const uint32_t* Al = Ah + TILE32;
        const uint32_t* Bh = Ah + 2 * TILE32;
        const uint32_t* Bl = Ah + 3 * TILE32;

        #pragma unroll
        for (int k16 = 0; k16 < 2; k16++) {
            const int ko = k16 * 8 + q;
            uint32_t af[4][4], bf[4][2];
            #pragma unroll
            for (int mt = 0; mt < 4; mt++) {
                int r = wr + mt * 16 + g;
                af[mt][0] = Ah[r * ROW32 + ko];
                af[mt][1] = Ah[(r + 8) * ROW32 + ko];
                af[mt][2] = Ah[r * ROW32 + ko + 4];
                af[mt][3] = Ah[(r + 8) * ROW32 + ko + 4];
            }
            #pragma unroll
            for (int nt = 0; nt < 4; nt++) {
                int n = wc + nt * 8 + g;
                bf[nt][0] = Bh[n * ROW32 + ko];
                bf[nt][1] = Bh[n * ROW32 + ko + 4];
            }
            #pragma unroll
            for (int mt = 0; mt < 4; mt++)
                #pragma unroll
                for (int nt = 0; nt < 4; nt++)
                    mma_bf16(acc[mt][nt], af[mt], bf[nt]);

            uint32_t bl[4][2];
            #pragma unroll
            for (int nt = 0; nt < 4; nt++) {
                int n = wc + nt * 8 + g;
                bl[nt][0] = Bl[n * ROW32 + ko];
                bl[nt][1] = Bl[n * ROW32 + ko + 4];
            }
            #pragma unroll
            for (int mt = 0; mt < 4; mt++)
                #pragma unroll
                for (int nt = 0; nt < 4; nt++)
                    mma_bf16(acc[mt][nt], af[mt], bl[nt]);

            uint32_t al[4][4];
            #pragma unroll
            for (int mt = 0; mt < 4; mt++) {
                int r = wr + mt * 16 + g;
                al[mt][0] = Al[r * ROW32 + ko];
                al[mt][1] = Al[(r + 8) * ROW32 + ko];
                al[mt][2] = Al[r * ROW32 + ko + 4];
                al[mt][3] = Al[(r + 8) * ROW32 + ko + 4];
            }
            #pragma unroll
            for (int mt = 0; mt < 4; mt++)
                #pragma unroll
                for (int nt = 0; nt < 4; nt++)
                    mma_bf16(acc[mt][nt], al[mt], bf[nt]);
        }
        __syncthreads();
        if (kc < 31) {
            store_chunk(smu, tid, pa, pb);
            __syncthreads();
        }
    }

    // ---- fused epilogue ----
    #pragma unroll
    for (int mt = 0; mt < 4; mt++) {
        #pragma unroll
        for (int half = 0; half < 2; half++) {
            const int m = m0 + wr + mt * 16 + half * 8 + g;
            float mz = 1.f;
            if (EPI == 2 || EPI == 3) mz = (mask[m] != 0) ? 0.f : 1.f;
            const int b_ = m >> 12;
            const int t  = m & (TT - 1);
            #pragma unroll
            for (int nt = 0; nt < 4; nt++) {
                const int c = n0 + wc + nt * 8 + q * 2;
                float v0 = acc[mt][nt][half * 2 + 0];
                float v1 = acc[mt][nt][half * 2 + 1];
                if (EPI == 1 || EPI == 2) {
                    v0 = (v0 > 0.f) ? (v0 + 1.f) : __expf(v0);
                    v1 = (v1 > 0.f) ? (v1 + 1.f) : __expf(v1);
                }
                if (EPI == 2 || EPI == 3) { v0 *= mz; v1 *= mz; }
                float2 w2 = make_float2(v0, v1);
                if (EPI == 0) {
                    *(float2*)(outp + (size_t)m * DD + c) = w2;
                } else {
                    const int h = c >> 6, e = c & 63;
                    *(float2*)(out + (((size_t)(b_ * HH + h)) * TT + t) * HD + e) = w2;
                }
            }
        }
    }
}

// ---------------------------------------------------------------------------
__global__ void zero_kv_kernel()
{
    int i = blockIdx.x * 256 + threadIdx.x;
    if (i < BB * HH * HD * HD) g_kv[i] = 0.f;
    if (i < BB * HH * HD)      g_ksum[i] = 0.f;
}

// ---------------------------------------------------------------------------
#define KV_NCH 8
__global__ __launch_bounds__(128)
void kv_kernel()
{
    const int bh  = blockIdx.x;
    const int ch  = blockIdx.y;
    const int tid = threadIdx.x;
    const int grp = tid >> 6;
    const int gt  = tid & 63;
    const int d0  = (gt >> 3) * 8;
    const int e0  = (gt & 7) * 8;
    const int RPB = TT / KV_NCH;
    const int RPG = RPB / 2;

    const float* kp = g_k + ((size_t)bh * TT + ch * RPB + grp * RPG) * HD;
    const float* vp = g_v + ((size_t)bh * TT + ch * RPB + grp * RPG) * HD;

    __shared__ float ks[2][8][64];
    __shared__ float vs[2][8][64];

    float acc[8][8];
    #pragma unroll
    for (int i = 0; i < 8; i++)
        #pragma unroll
        for (int j = 0; j < 8; j++) acc[i][j] = 0.f;
    float ksacc = 0.f;

    for (int t0 = 0; t0 < RPG; t0 += 8) {
        #pragma unroll
        for (int l = 0; l < 2; l++) {
            int f = gt + l * 64;
            int r = f >> 4, c = (f & 15) * 4;
            *(float4*)&ks[grp][r][c] = *(const float4*)(kp + (size_t)(t0 + r) * HD + c);
            *(float4*)&vs[grp][r][c] = *(const float4*)(vp + (size_t)(t0 + r) * HD + c);
        }
        __syncthreads();
        #pragma unroll
        for (int tt = 0; tt < 8; tt++) {
            float kr[8], vr[8];
            *(float4*)(kr)     = *(const float4*)&ks[grp][tt][d0];
            *(float4*)(kr + 4) = *(const float4*)&ks[grp][tt][d0 + 4];
            *(float4*)(vr)     = *(const float4*)&vs[grp][tt][e0];
            *(float4*)(vr + 4) = *(const float4*)&vs[grp][tt][e0 + 4];
            #pragma unroll
            for (int i = 0; i < 8; i++)
                #pragma unroll
                for (int j = 0; j < 8; j++) acc[i][j] += kr[i] * vr[j];
            ksacc += ks[grp][tt][gt];
        }
        __syncthreads();
    }

    float* kvp = g_kv + (size_t)bh * HD * HD;
    #pragma unroll
    for (int i = 0; i < 8; i++)
        #pragma unroll
        for (int j = 0; j < 8; j++)
            atomicAdd(&kvp[(d0 + i) * HD + e0 + j], acc[i][j]);
    atomicAdd(&g_ksum[bh * HD + gt], ksacc);
}

// ---------------------------------------------------------------------------
__global__ __launch_bounds__(256)
void out_kernel()
{
    const int bh  = blockIdx.y;
    const int t0  = blockIdx.x * 128;
    const int tid = threadIdx.x;

    __shared__ float kvs[64][64];
    __shared__ float kss[64];

    const float* kvp = g_kv + (size_t)bh * HD * HD;
    #pragma unroll
    for (int l = 0; l < 4; l++) {
        int f = tid + l * 256;
        int r = f >> 4, c = (f & 15) * 4;
        *(float4*)&kvs[r][c] = *(const float4*)(kvp + r * HD + c);
    }
    if (tid < 64) kss[tid] = g_ksum[bh * HD + tid];
    __syncthreads();

    const int row = tid >> 1;
    const int c0  = (tid & 1) * 32;
    const float* qp = g_q + ((size_t)bh * TT + t0 + row) * HD;

    float acc[32];
    #pragma unroll
    for (int j = 0; j < 32; j++) acc[j] = 0.f;
    float norm = 0.f;

    #pragma unroll
    for (int dq = 0; dq < 64; dq += 4) {
        float4 q4 = *(const float4*)(qp + dq);
        float qa[4] = {q4.x, q4.y, q4.z, q4.w};
        #pragma unroll
        for (int s = 0; s < 4; s++) {
            int d = dq + s;
            norm += qa[s] * kss[d];
            #pragma unroll
            for (int j = 0; j < 32; j++) acc[j] += qa[s] * kvs[d][c0 + j];
        }
    }

    float inv = 1.f / fmaxf(norm, 1e-6f);
    const int b_ = bh >> 4, h = bh & 15;
    float* op = g_attn + ((size_t)b_ * TT + t0 + row) * DD + h * HD + c0;
    #pragma unroll
    for (int j = 0; j < 32; j++) op[j] = acc[j] * inv;
}

// ---------------------------------------------------------------------------
extern "C" void kernel_launch(void* const* d_in, const int* in_sizes, int n_in,
                              void* d_out, int out_size)
{
    const float* x  = (const float*)d_in[0];
    const int*   mk = (const int*)d_in[1];       // bool mask promoted to int32
    const float* Wq = (const float*)d_in[2];
    const float* Wk = (const float*)d_in[3];
    const float* Wv = (const float*)d_in[4];
    const float* Wo = (const float*)d_in[5];
    float* out      = (float*)d_out;

    dim3 gg(DD / 128, MM / 128);   // (8, 128): x = n-tile fastest -> A-stripe L2 reuse

    sgemm_mma<1><<<gg, 256>>>(x, Wq, mk, nullptr);   // q = phi(x Wq^T)
    sgemm_mma<2><<<gg, 256>>>(x, Wk, mk, nullptr);   // k = phi(x Wk^T)*m
    sgemm_mma<3><<<gg, 256>>>(x, Wv, mk, nullptr);   // v = (x Wv^T)*m

    zero_kv_kernel<<<(BB * HH * HD * HD + 255) / 256, 256>>>();
    kv_kernel<<<dim3(BB * HH, KV_NCH), 128>>>();
    out_kernel<<<dim3(TT / 128, BB * HH), 256>>>();

    sgemm_mma<0><<<gg, 256>>>(nullptr, Wo, mk, out); // y = attn Wo^T
}